// round 15
// baseline (speedup 1.0000x reference)
#include <cuda_runtime.h>
#include <cuda_fp16.h>
#include <math.h>
#include <stdint.h>

#define VSZ 8192
#define SA_STRB 1040
#define SB_STRB 144
#define NRPAD 112
#define A_BYTES (NRPAD * SA_STRB)          // 116480
#define B_BYTES (256 * SB_STRB)            // 36864
#define DYN_SMEM (A_BYTES + 2 * B_BYTES)   // 190208

__device__ float g_enc[512 * 512];
__device__ float g_dec[128 * 512];
__device__ __half g_wvt[8192 * 512];   // [v][d] fp16

__device__ __forceinline__ uint32_t smem_u32(const void* p) {
    uint32_t a;
    asm("{ .reg .u64 t; cvta.to.shared.u64 t, %1; cvt.u32.u64 %0, t; }" : "=r"(a) : "l"(p));
    return a;
}
__device__ __forceinline__ void cpa16(uint32_t dst, const void* src) {
    asm volatile("cp.async.cg.shared.global [%0], [%1], 16;" :: "r"(dst), "l"(src));
}
#define CPA_COMMIT() asm volatile("cp.async.commit_group;" ::: "memory")
#define CPA_WAIT1()  asm volatile("cp.async.wait_group 1;" ::: "memory")
#define CPA_WAIT0()  asm volatile("cp.async.wait_group 0;" ::: "memory")
__device__ __forceinline__ void ldsm4(uint32_t* r, uint32_t a) {
    asm volatile("ldmatrix.sync.aligned.m8n8.x4.shared.b16 {%0,%1,%2,%3}, [%4];"
        : "=r"(r[0]), "=r"(r[1]), "=r"(r[2]), "=r"(r[3]) : "r"(a));
}
__device__ __forceinline__ void mma_h(uint32_t* c, const uint32_t* a, const uint32_t* b) {
    asm("mma.sync.aligned.m16n8k16.row.col.f16.f16.f16.f16 "
        "{%0,%1}, {%2,%3,%4,%5}, {%6,%7}, {%0,%1};\n"
        : "+r"(c[0]), "+r"(c[1])
        : "r"(a[0]), "r"(a[1]), "r"(a[2]), "r"(a[3]), "r"(b[0]), "r"(b[1]));
}

// ---------------- merged prep: encdec (bid<640) + Wv cvt (bid>=640) ----------------
__global__ void k_prep(const float* __restrict__ v, const float* __restrict__ t,
                       const float* __restrict__ W1, const float* __restrict__ b1,
                       const float* __restrict__ W2, const float* __restrict__ b2,
                       const float* __restrict__ Wv) {
    __shared__ float xr[4][512];
    int bid = blockIdx.x, tid = threadIdx.x;
    if (bid < 640) {
        int rg = bid >> 2, cq = bid & 3;
        const float *in, *W, *bs; float* out;
        if (rg < 128) { in = v + (size_t)rg * 2048; W = W1; bs = b1; out = g_enc + (size_t)rg * 2048; }
        else { in = t + (size_t)(rg - 128) * 2048; W = W2; bs = b2; out = g_dec + (size_t)(rg - 128) * 2048; }
        #pragma unroll
        for (int i = 0; i < 8; ++i) ((float*)xr)[i * 256 + tid] = in[i * 256 + tid];
        __syncthreads();
        int c = cq * 128 + (tid & 127);
        int rp = tid >> 7;
        float bb = bs[c];
        float a0 = bb, a1 = bb, a0b = 0.f, a1b = 0.f;
        #pragma unroll 4
        for (int d = 0; d < 512; d += 2) {
            float w0 = W[d * 512 + c], w1 = W[(d + 1) * 512 + c];
            a0  = fmaf(xr[rp][d],     w0, a0);
            a0b = fmaf(xr[rp][d + 1], w1, a0b);
            a1  = fmaf(xr[rp + 2][d],     w0, a1);
            a1b = fmaf(xr[rp + 2][d + 1], w1, a1b);
        }
        out[(size_t)rp * 512 + c] = a0 + a0b;
        out[(size_t)(rp + 2) * 512 + c] = a1 + a1b;
    } else {
        float (*tile)[33] = (float(*)[33])xr;
        int b2i = bid - 640;
        int bvi = b2i & 255, bd = b2i >> 8;
        int v0 = bvi * 32, d0 = bd * 32;
        int c = tid & 31, r8 = tid >> 5;
        #pragma unroll
        for (int i = 0; i < 4; ++i)
            tile[i * 8 + r8][c] = Wv[(size_t)(d0 + i * 8 + r8) * VSZ + v0 + c];
        __syncthreads();
        #pragma unroll
        for (int i = 0; i < 4; ++i)
            g_wvt[(size_t)(v0 + i * 8 + r8) * 512 + d0 + c] = __float2half(tile[c][i * 8 + r8]);
    }
}

// ---- main fp16 GEMM + fused log-softmax; grid 296 = 2x148 balanced waves ----
// CTA: 110/111 rows (padded tile 112) x full V. 8 warps 2(M)x4(N);
// wm0 owns rows 0..63 (4 am-groups), wm1 owns rows 64..111 (3 am-groups).
__global__ void __launch_bounds__(256, 1)
k_gemm2(const float* __restrict__ bv, float* __restrict__ out) {
    extern __shared__ char sm[];
    __shared__ float pmax[4][NRPAD], psum[4][NRPAD];
    __shared__ float rmax[NRPAD], rsum[NRPAD], slse[NRPAD];

    const uint32_t sA = smem_u32(sm);
    const uint32_t sB0 = sA + A_BYTES;
    int tid = threadIdx.x, lane = tid & 31, w = tid >> 5;
    int wm = w >> 2, wn = w & 3;
    int q = lane >> 2, l4 = lane & 3;
    int bid = blockIdx.x;
    int nrows = (bid < 208) ? 111 : 110;
    int r0 = (bid < 208) ? bid * 111 : 23088 + (bid - 208) * 110;
    int nam = 4 - wm;          // wm0: 4 groups, wm1: 3 groups

    // ---- build A tile (relu(enc+dec) -> fp16), pad rows zero ----
    #pragma unroll 1
    for (int i = 0; i < 28; ++i) {
        int idx = i * 256 + tid;
        int r = idx >> 6, g = idx & 63;
        uint4 u = make_uint4(0u, 0u, 0u, 0u);
        if (r < nrows) {
            int grow = r0 + r;
            const float* ep = g_enc + (size_t)(grow >> 6) * 512 + g * 8;
            const float* dp = g_dec + (size_t)(((grow >> 14) << 6) | (grow & 63)) * 512 + g * 8;
            float4 e0 = *(const float4*)ep, e1 = *(const float4*)(ep + 4);
            float4 d0 = *(const float4*)dp, d1 = *(const float4*)(dp + 4);
            __half2 p0 = __floats2half2_rn(fmaxf(e0.x + d0.x, 0.f), fmaxf(e0.y + d0.y, 0.f));
            __half2 p1 = __floats2half2_rn(fmaxf(e0.z + d0.z, 0.f), fmaxf(e0.w + d0.w, 0.f));
            __half2 p2 = __floats2half2_rn(fmaxf(e1.x + d1.x, 0.f), fmaxf(e1.y + d1.y, 0.f));
            __half2 p3 = __floats2half2_rn(fmaxf(e1.z + d1.z, 0.f), fmaxf(e1.w + d1.w, 0.f));
            u.x = *(unsigned*)&p0; u.y = *(unsigned*)&p1; u.z = *(unsigned*)&p2; u.w = *(unsigned*)&p3;
        }
        *(uint4*)(sm + r * SA_STRB + g * 16) = u;
    }
    if (tid < NRPAD) { rmax[tid] = -1e30f; rsum[tid] = 0.f; }

    const uint32_t aBase = sA + (wm * 64 + (lane & 15)) * SA_STRB + (lane >> 4) * 16;
    const int bN = (lane & 7) + ((lane >> 4) << 3);
    const uint32_t bKh = ((lane >> 3) & 1) * 16;
    const uint32_t bBase = sB0 + (wn * 64 + bN) * SB_STRB + bKh;

    uint32_t acc[4][8][2];

    // stage slab 0
    #pragma unroll
    for (int i = 0; i < 8; ++i) {
        int flat = i * 256 + tid;
        int n = flat >> 3, c = flat & 7;
        cpa16(sB0 + n * SB_STRB + c * 16, (const char*)g_wvt + (size_t)n * 1024 + c * 16);
    }
    CPA_COMMIT();

    #pragma unroll 1
    for (int s = 0; s < 256; ++s) {
        int vc = s >> 3, kb = s & 7, buf = s & 1;
        __syncthreads();
        if (s + 1 < 256) {
            int vn = (s + 1) >> 3, kn = (s + 1) & 7;
            uint32_t dst = sB0 + ((s + 1) & 1) * B_BYTES;
            const char* src = (const char*)g_wvt + (size_t)vn * 256 * 1024 + kn * 128;
            #pragma unroll
            for (int i = 0; i < 8; ++i) {
                int flat = i * 256 + tid;
                int n = flat >> 3, c = flat & 7;
                cpa16(dst + n * SB_STRB + c * 16, src + (size_t)n * 1024 + c * 16);
            }
            CPA_COMMIT();
            CPA_WAIT1();
        } else {
            CPA_WAIT0();
        }
        __syncthreads();

        if (kb == 0) {
            #pragma unroll
            for (int am = 0; am < 4; ++am)
                #pragma unroll
                for (int an = 0; an < 8; ++an) { acc[am][an][0] = 0u; acc[am][an][1] = 0u; }
        }

        uint32_t bB = bBase + buf * B_BYTES;
        uint32_t aK = aBase + kb * 128;
        #pragma unroll
        for (int ks = 0; ks < 4; ++ks) {
            uint32_t afr[4][4], bfr[4][4];
            #pragma unroll
            for (int am = 0; am < 4; ++am)
                if (am < nam) ldsm4(afr[am], aK + am * 16 * SA_STRB + ks * 32);
            #pragma unroll
            for (int t = 0; t < 4; ++t) ldsm4(bfr[t], bB + t * 16 * SB_STRB + ks * 32);
            #pragma unroll
            for (int am = 0; am < 4; ++am)
                if (am < nam)
                    #pragma unroll
                    for (int t = 0; t < 4; ++t) {
                        mma_h(acc[am][2 * t],     afr[am], &bfr[t][0]);
                        mma_h(acc[am][2 * t + 1], afr[am], &bfr[t][2]);
                    }
        }

        if (kb == 7) {
            int v0 = vc * 256;
            float2 bvv[8];
            #pragma unroll
            for (int an = 0; an < 8; ++an)
                bvv[an] = *(const float2*)&bv[v0 + wn * 64 + an * 8 + l4 * 2];
            #pragma unroll
            for (int am = 0; am < 4; ++am) {
                if (am >= nam) break;
                int rowl = wm * 64 + am * 16 + q;
                bool v0ok = rowl < nrows, v1ok = (rowl + 8) < nrows;
                size_t gr0 = (size_t)(r0 + rowl) << 13;
                size_t gr1 = gr0 + (8u << 13);
                float mx0 = -1e30f, mx1 = -1e30f;
                float z[8][4];
                #pragma unroll
                for (int an = 0; an < 8; ++an) {
                    float2 f0 = __half22float2(*(__half2*)&acc[am][an][0]);
                    float2 f1 = __half22float2(*(__half2*)&acc[am][an][1]);
                    z[an][0] = f0.x + bvv[an].x; z[an][1] = f0.y + bvv[an].y;
                    z[an][2] = f1.x + bvv[an].x; z[an][3] = f1.y + bvv[an].y;
                    size_t coff = v0 + wn * 64 + an * 8 + l4 * 2;
                    if (v0ok) *(float2*)&out[gr0 + coff] = make_float2(z[an][0], z[an][1]);
                    if (v1ok) *(float2*)&out[gr1 + coff] = make_float2(z[an][2], z[an][3]);
                    mx0 = fmaxf(mx0, fmaxf(z[an][0], z[an][1]));
                    mx1 = fmaxf(mx1, fmaxf(z[an][2], z[an][3]));
                }
                mx0 = fmaxf(mx0, __shfl_xor_sync(~0u, mx0, 1));
                mx0 = fmaxf(mx0, __shfl_xor_sync(~0u, mx0, 2));
                mx1 = fmaxf(mx1, __shfl_xor_sync(~0u, mx1, 1));
                mx1 = fmaxf(mx1, __shfl_xor_sync(~0u, mx1, 2));
                float s0 = 0.f, s1 = 0.f;
                #pragma unroll
                for (int an = 0; an < 8; ++an) {
                    s0 += __expf(z[an][0] - mx0) + __expf(z[an][1] - mx0);
                    s1 += __expf(z[an][2] - mx1) + __expf(z[an][3] - mx1);
                }
                s0 += __shfl_xor_sync(~0u, s0, 1);
                s0 += __shfl_xor_sync(~0u, s0, 2);
                s1 += __shfl_xor_sync(~0u, s1, 1);
                s1 += __shfl_xor_sync(~0u, s1, 2);
                if (l4 == 0) {
                    pmax[wn][rowl] = mx0;     psum[wn][rowl] = s0;
                    pmax[wn][rowl + 8] = mx1; psum[wn][rowl + 8] = s1;
                }
            }
            __syncthreads();
            if (tid < NRPAD) {
                float m0 = pmax[0][tid], m1 = pmax[1][tid];
                float m2 = pmax[2][tid], m3 = pmax[3][tid];
                float mo = rmax[tid];
                float mn = fmaxf(fmaxf(fmaxf(m0, m1), fmaxf(m2, m3)), mo);
                rsum[tid] = rsum[tid] * __expf(mo - mn)
                          + psum[0][tid] * __expf(m0 - mn)
                          + psum[1][tid] * __expf(m1 - mn)
                          + psum[2][tid] * __expf(m2 - mn)
                          + psum[3][tid] * __expf(m3 - mn);
                rmax[tid] = mn;
            }
        }
    }

    // ---- fused fixup: out -= lse over this CTA's nrows rows ----
    __syncthreads();
    if (tid < NRPAD) slse[tid] = rmax[tid] + logf(rsum[tid]);
    __syncthreads();
    int nf4 = nrows << 11;                   // nrows * 2048 float4
    float4* ob = (float4*)(out + ((size_t)r0 << 13));
    #pragma unroll 1
    for (int it = 0; it < 896; ++it) {
        int idx = it * 256 + tid;
        if (idx < nf4) {
            float l = slse[idx >> 11];
            float4 x = ob[idx];
            x.x -= l; x.y -= l; x.z -= l; x.w -= l;
            ob[idx] = x;
        }
    }
}

extern "C" void kernel_launch(void* const* d_in, const int* in_sizes, int n_in,
                              void* d_out, int out_size) {
    (void)in_sizes; (void)n_in; (void)out_size;
    const float* v  = (const float*)d_in[0];
    const float* t  = (const float*)d_in[1];
    const float* W1 = (const float*)d_in[2];
    const float* b1 = (const float*)d_in[3];
    const float* W2 = (const float*)d_in[4];
    const float* b2 = (const float*)d_in[5];
    const float* Wv = (const float*)d_in[6];
    const float* bvp = (const float*)d_in[7];
    float* out = (float*)d_out;

    k_prep<<<4736, 256>>>(v, t, W1, b1, W2, b2, Wv);
    cudaFuncSetAttribute(k_gemm2, cudaFuncAttributeMaxDynamicSharedMemorySize, DYN_SMEM);
    k_gemm2<<<296, 256, DYN_SMEM>>>(bvp, out);
}

// round 16
// speedup vs baseline: 1.0254x; 1.0254x over previous
#include <cuda_runtime.h>
#include <cuda_fp16.h>
#include <math.h>
#include <stdint.h>

#define VSZ 8192
#define SA_STRB 1040
#define SB_STRB 144
#define NRPAD 112
#define A_BYTES (NRPAD * SA_STRB)          // 116480
#define B_BYTES (256 * SB_STRB)            // 36864
#define DYN_SMEM (A_BYTES + 2 * B_BYTES)   // 190208

__device__ float g_enc[512 * 512];
__device__ float g_dec[128 * 512];
__device__ __half g_wvt[8192 * 512];   // [v][d] fp16

__device__ __forceinline__ uint32_t smem_u32(const void* p) {
    uint32_t a;
    asm("{ .reg .u64 t; cvta.to.shared.u64 t, %1; cvt.u32.u64 %0, t; }" : "=r"(a) : "l"(p));
    return a;
}
__device__ __forceinline__ void cpa16(uint32_t dst, const void* src) {
    asm volatile("cp.async.cg.shared.global [%0], [%1], 16;" :: "r"(dst), "l"(src));
}
#define CPA_COMMIT() asm volatile("cp.async.commit_group;" ::: "memory")
#define CPA_WAIT1()  asm volatile("cp.async.wait_group 1;" ::: "memory")
#define CPA_WAIT0()  asm volatile("cp.async.wait_group 0;" ::: "memory")
__device__ __forceinline__ void ldsm4(uint32_t* r, uint32_t a) {
    asm volatile("ldmatrix.sync.aligned.m8n8.x4.shared.b16 {%0,%1,%2,%3}, [%4];"
        : "=r"(r[0]), "=r"(r[1]), "=r"(r[2]), "=r"(r[3]) : "r"(a));
}
__device__ __forceinline__ void mma_h(uint32_t* c, const uint32_t* a, const uint32_t* b) {
    asm("mma.sync.aligned.m16n8k16.row.col.f16.f16.f16.f16 "
        "{%0,%1}, {%2,%3,%4,%5}, {%6,%7}, {%0,%1};\n"
        : "+r"(c[0]), "+r"(c[1])
        : "r"(a[0]), "r"(a[1]), "r"(a[2]), "r"(a[3]), "r"(b[0]), "r"(b[1]));
}

// ---------------- merged prep: encdec (bid<640) + Wv cvt (bid>=640) ----------------
__global__ void k_prep(const float* __restrict__ v, const float* __restrict__ t,
                       const float* __restrict__ W1, const float* __restrict__ b1,
                       const float* __restrict__ W2, const float* __restrict__ b2,
                       const float* __restrict__ Wv) {
    __shared__ float xr[4][512];
    int bid = blockIdx.x, tid = threadIdx.x;
    if (bid < 640) {
        int rg = bid >> 2, cq = bid & 3;
        const float *in, *W, *bs; float* out;
        if (rg < 128) { in = v + (size_t)rg * 2048; W = W1; bs = b1; out = g_enc + (size_t)rg * 2048; }
        else { in = t + (size_t)(rg - 128) * 2048; W = W2; bs = b2; out = g_dec + (size_t)(rg - 128) * 2048; }
        #pragma unroll
        for (int i = 0; i < 8; ++i) ((float*)xr)[i * 256 + tid] = in[i * 256 + tid];
        __syncthreads();
        int c = cq * 128 + (tid & 127);
        int rp = tid >> 7;
        float bb = bs[c];
        float a0 = bb, a1 = bb, a0b = 0.f, a1b = 0.f;
        #pragma unroll 4
        for (int d = 0; d < 512; d += 2) {
            float w0 = W[d * 512 + c], w1 = W[(d + 1) * 512 + c];
            a0  = fmaf(xr[rp][d],     w0, a0);
            a0b = fmaf(xr[rp][d + 1], w1, a0b);
            a1  = fmaf(xr[rp + 2][d],     w0, a1);
            a1b = fmaf(xr[rp + 2][d + 1], w1, a1b);
        }
        out[(size_t)rp * 512 + c] = a0 + a0b;
        out[(size_t)(rp + 2) * 512 + c] = a1 + a1b;
    } else {
        float (*tile)[33] = (float(*)[33])xr;
        int b2i = bid - 640;
        int bvi = b2i & 255, bd = b2i >> 8;
        int v0 = bvi * 32, d0 = bd * 32;
        int c = tid & 31, r8 = tid >> 5;
        #pragma unroll
        for (int i = 0; i < 4; ++i)
            tile[i * 8 + r8][c] = Wv[(size_t)(d0 + i * 8 + r8) * VSZ + v0 + c];
        __syncthreads();
        #pragma unroll
        for (int i = 0; i < 4; ++i)
            g_wvt[(size_t)(v0 + i * 8 + r8) * 512 + d0 + c] = __float2half(tile[c][i * 8 + r8]);
    }
}

// ---------------- compile-time specialized tensor paths ----------------
template<int NAM>
__device__ __forceinline__ void t_mma(uint32_t (&acc)[4][8][2], uint32_t aK, uint32_t bB) {
    #pragma unroll
    for (int ks = 0; ks < 4; ++ks) {
        uint32_t afr[NAM][4], bfr[4][4];
        #pragma unroll
        for (int am = 0; am < NAM; ++am) ldsm4(afr[am], aK + am * 16 * SA_STRB + ks * 32);
        #pragma unroll
        for (int t = 0; t < 4; ++t) ldsm4(bfr[t], bB + t * 16 * SB_STRB + ks * 32);
        #pragma unroll
        for (int am = 0; am < NAM; ++am)
            #pragma unroll
            for (int t = 0; t < 4; ++t) {
                mma_h(acc[am][2 * t],     afr[am], &bfr[t][0]);
                mma_h(acc[am][2 * t + 1], afr[am], &bfr[t][2]);
            }
    }
}

template<int NAM>
__device__ __forceinline__ void t_epi(uint32_t (&acc)[4][8][2], int v0w, int rbase,
                                      int q, int l4, int r0, int nrows,
                                      float* __restrict__ out, const float* __restrict__ bv,
                                      float* pmaxr, float* psumr) {
    #pragma unroll
    for (int am = 0; am < NAM; ++am) {
        int rowl = rbase + am * 16 + q;
        bool ok0 = rowl < nrows, ok1 = (rowl + 8) < nrows;
        size_t gr0 = (size_t)(r0 + rowl) << 13;
        size_t gr1 = gr0 + (8u << 13);
        float mx0 = -1e30f, mx1 = -1e30f;
        #pragma unroll
        for (int an = 0; an < 8; ++an) {
            int cc = v0w + an * 8 + l4 * 2;
            float2 bv2 = __ldg((const float2*)&bv[cc]);
            float2 f0 = __half22float2(*(__half2*)&acc[am][an][0]);
            float2 f1 = __half22float2(*(__half2*)&acc[am][an][1]);
            float z0 = f0.x + bv2.x, z1 = f0.y + bv2.y;
            float z2 = f1.x + bv2.x, z3 = f1.y + bv2.y;
            if (ok0) *(float2*)&out[gr0 + cc] = make_float2(z0, z1);
            if (ok1) *(float2*)&out[gr1 + cc] = make_float2(z2, z3);
            mx0 = fmaxf(mx0, fmaxf(z0, z1));
            mx1 = fmaxf(mx1, fmaxf(z2, z3));
        }
        mx0 = fmaxf(mx0, __shfl_xor_sync(~0u, mx0, 1));
        mx0 = fmaxf(mx0, __shfl_xor_sync(~0u, mx0, 2));
        mx1 = fmaxf(mx1, __shfl_xor_sync(~0u, mx1, 1));
        mx1 = fmaxf(mx1, __shfl_xor_sync(~0u, mx1, 2));
        float s0 = 0.f, s1 = 0.f;
        #pragma unroll
        for (int an = 0; an < 8; ++an) {
            int cc = v0w + an * 8 + l4 * 2;
            float2 bv2 = __ldg((const float2*)&bv[cc]);
            float2 f0 = __half22float2(*(__half2*)&acc[am][an][0]);
            float2 f1 = __half22float2(*(__half2*)&acc[am][an][1]);
            s0 += __expf(f0.x + bv2.x - mx0) + __expf(f0.y + bv2.y - mx0);
            s1 += __expf(f1.x + bv2.x - mx1) + __expf(f1.y + bv2.y - mx1);
        }
        s0 += __shfl_xor_sync(~0u, s0, 1);
        s0 += __shfl_xor_sync(~0u, s0, 2);
        s1 += __shfl_xor_sync(~0u, s1, 1);
        s1 += __shfl_xor_sync(~0u, s1, 2);
        if (l4 == 0) {
            pmaxr[rowl] = mx0;     psumr[rowl] = s0;
            pmaxr[rowl + 8] = mx1; psumr[rowl + 8] = s1;
        }
    }
}

// ---- main fp16 GEMM + fused log-softmax; grid 296 = 2x148 balanced waves ----
// CTA: 110/111 rows (tile padded to 112). wm0 warps: rows 0..63 (t_mma<4>);
// wm1 warps: rows 64..111 (t_mma<3>). Each SMSP carries one of each -> 7 groups.
__global__ void __launch_bounds__(256, 1)
k_gemm2(const float* __restrict__ bv, float* __restrict__ out) {
    extern __shared__ char sm[];
    __shared__ float pmax[4][NRPAD], psum[4][NRPAD];
    __shared__ float rmax[NRPAD], rsum[NRPAD], slse[NRPAD];

    const uint32_t sA = smem_u32(sm);
    const uint32_t sB0 = sA + A_BYTES;
    int tid = threadIdx.x, lane = tid & 31, w = tid >> 5;
    int wm = w >> 2, wn = w & 3;
    int q = lane >> 2, l4 = lane & 3;
    int bid = blockIdx.x;
    int nrows = (bid < 208) ? 111 : 110;
    int r0 = (bid < 208) ? bid * 111 : 23088 + (bid - 208) * 110;

    // ---- build A tile (relu(enc+dec) -> fp16), pad rows zero ----
    #pragma unroll 1
    for (int i = 0; i < 28; ++i) {
        int idx = i * 256 + tid;
        int r = idx >> 6, g = idx & 63;
        uint4 u = make_uint4(0u, 0u, 0u, 0u);
        if (r < nrows) {
            int grow = r0 + r;
            const float* ep = g_enc + (size_t)(grow >> 6) * 512 + g * 8;
            const float* dp = g_dec + (size_t)(((grow >> 14) << 6) | (grow & 63)) * 512 + g * 8;
            float4 e0 = *(const float4*)ep, e1 = *(const float4*)(ep + 4);
            float4 d0 = *(const float4*)dp, d1 = *(const float4*)(dp + 4);
            __half2 p0 = __floats2half2_rn(fmaxf(e0.x + d0.x, 0.f), fmaxf(e0.y + d0.y, 0.f));
            __half2 p1 = __floats2half2_rn(fmaxf(e0.z + d0.z, 0.f), fmaxf(e0.w + d0.w, 0.f));
            __half2 p2 = __floats2half2_rn(fmaxf(e1.x + d1.x, 0.f), fmaxf(e1.y + d1.y, 0.f));
            __half2 p3 = __floats2half2_rn(fmaxf(e1.z + d1.z, 0.f), fmaxf(e1.w + d1.w, 0.f));
            u.x = *(unsigned*)&p0; u.y = *(unsigned*)&p1; u.z = *(unsigned*)&p2; u.w = *(unsigned*)&p3;
        }
        *(uint4*)(sm + r * SA_STRB + g * 16) = u;
    }
    if (tid < NRPAD) { rmax[tid] = -1e30f; rsum[tid] = 0.f; }

    const uint32_t aBase = sA + (wm * 64 + (lane & 15)) * SA_STRB + (lane >> 4) * 16;
    const int bN = (lane & 7) + ((lane >> 4) << 3);
    const uint32_t bKh = ((lane >> 3) & 1) * 16;
    const uint32_t bBase = sB0 + (wn * 64 + bN) * SB_STRB + bKh;

    uint32_t acc[4][8][2];

    // stage slab 0
    #pragma unroll
    for (int i = 0; i < 8; ++i) {
        int flat = i * 256 + tid;
        int n = flat >> 3, c = flat & 7;
        cpa16(sB0 + n * SB_STRB + c * 16, (const char*)g_wvt + (size_t)n * 1024 + c * 16);
    }
    CPA_COMMIT();

    #pragma unroll 1
    for (int s = 0; s < 256; ++s) {
        int vc = s >> 3, kb = s & 7, buf = s & 1;
        __syncthreads();
        if (s + 1 < 256) {
            int vn = (s + 1) >> 3, kn = (s + 1) & 7;
            uint32_t dst = sB0 + ((s + 1) & 1) * B_BYTES;
            const char* src = (const char*)g_wvt + (size_t)vn * 256 * 1024 + kn * 128;
            #pragma unroll
            for (int i = 0; i < 8; ++i) {
                int flat = i * 256 + tid;
                int n = flat >> 3, c = flat & 7;
                cpa16(dst + n * SB_STRB + c * 16, src + (size_t)n * 1024 + c * 16);
            }
            CPA_COMMIT();
            CPA_WAIT1();
        } else {
            CPA_WAIT0();
        }
        __syncthreads();

        if (kb == 0) {
            #pragma unroll
            for (int am = 0; am < 4; ++am)
                #pragma unroll
                for (int an = 0; an < 8; ++an) { acc[am][an][0] = 0u; acc[am][an][1] = 0u; }
        }

        uint32_t bB = bBase + buf * B_BYTES;
        uint32_t aK = aBase + kb * 128;
        if (wm == 0) t_mma<4>(acc, aK, bB);
        else         t_mma<3>(acc, aK, bB);

        if (kb == 7) {
            int v0w = vc * 256 + wn * 64;
            if (wm == 0) t_epi<4>(acc, v0w, 0,  q, l4, r0, nrows, out, bv, &pmax[wn][0], &psum[wn][0]);
            else         t_epi<3>(acc, v0w, 64, q, l4, r0, nrows, out, bv, &pmax[wn][0], &psum[wn][0]);
            __syncthreads();
            if (tid < NRPAD) {
                float m0 = pmax[0][tid], m1 = pmax[1][tid];
                float m2 = pmax[2][tid], m3 = pmax[3][tid];
                float mo = rmax[tid];
                float mn = fmaxf(fmaxf(fmaxf(m0, m1), fmaxf(m2, m3)), mo);
                rsum[tid] = rsum[tid] * __expf(mo - mn)
                          + psum[0][tid] * __expf(m0 - mn)
                          + psum[1][tid] * __expf(m1 - mn)
                          + psum[2][tid] * __expf(m2 - mn)
                          + psum[3][tid] * __expf(m3 - mn);
                rmax[tid] = mn;
            }
        }
    }

    // ---- fused fixup: out -= lse over this CTA's nrows rows ----
    __syncthreads();
    if (tid < NRPAD) slse[tid] = rmax[tid] + logf(rsum[tid]);
    __syncthreads();
    int nf4 = nrows << 11;
    float4* ob = (float4*)(out + ((size_t)r0 << 13));
    #pragma unroll 1
    for (int it = 0; it < 888; ++it) {
        int idx = it * 256 + tid;
        if (idx < nf4) {
            float l = slse[idx >> 11];
            float4 x = ob[idx];
            x.x -= l; x.y -= l; x.z -= l; x.w -= l;
            ob[idx] = x;
        }
    }
}

extern "C" void kernel_launch(void* const* d_in, const int* in_sizes, int n_in,
                              void* d_out, int out_size) {
    (void)in_sizes; (void)n_in; (void)out_size;
    const float* v  = (const float*)d_in[0];
    const float* t  = (const float*)d_in[1];
    const float* W1 = (const float*)d_in[2];
    const float* b1 = (const float*)d_in[3];
    const float* W2 = (const float*)d_in[4];
    const float* b2 = (const float*)d_in[5];
    const float* Wv = (const float*)d_in[6];
    const float* bvp = (const float*)d_in[7];
    float* out = (float*)d_out;

    k_prep<<<4736, 256>>>(v, t, W1, b1, W2, b2, Wv);
    cudaFuncSetAttribute(k_gemm2, cudaFuncAttributeMaxDynamicSharedMemorySize, DYN_SMEM);
    k_gemm2<<<296, 256, DYN_SMEM>>>(bvp, out);
}

// round 17
// speedup vs baseline: 1.3173x; 1.2847x over previous
#include <cuda_runtime.h>
#include <cuda_fp16.h>
#include <math.h>
#include <stdint.h>

#define VSZ 8192
#define SA_STRB 1040
#define SB_STRB 144
#define A_BYTES (128 * SA_STRB)
#define B_BYTES (256 * SB_STRB)
#define DYN_SMEM (A_BYTES + 2 * B_BYTES)

__device__ float g_enc[512 * 512];
__device__ float g_dec[128 * 512];
__device__ __half g_wvt[8192 * 512];   // [v][d] fp16

__device__ __forceinline__ uint32_t smem_u32(const void* p) {
    uint32_t a;
    asm("{ .reg .u64 t; cvta.to.shared.u64 t, %1; cvt.u32.u64 %0, t; }" : "=r"(a) : "l"(p));
    return a;
}
__device__ __forceinline__ void cpa16(uint32_t dst, const void* src) {
    asm volatile("cp.async.cg.shared.global [%0], [%1], 16;" :: "r"(dst), "l"(src));
}
#define CPA_COMMIT() asm volatile("cp.async.commit_group;" ::: "memory")
#define CPA_WAIT1()  asm volatile("cp.async.wait_group 1;" ::: "memory")
#define CPA_WAIT0()  asm volatile("cp.async.wait_group 0;" ::: "memory")
__device__ __forceinline__ void ldsm4(uint32_t* r, uint32_t a) {
    asm volatile("ldmatrix.sync.aligned.m8n8.x4.shared.b16 {%0,%1,%2,%3}, [%4];"
        : "=r"(r[0]), "=r"(r[1]), "=r"(r[2]), "=r"(r[3]) : "r"(a));
}
__device__ __forceinline__ void mma_h(uint32_t* c, const uint32_t* a, const uint32_t* b) {
    asm("mma.sync.aligned.m16n8k16.row.col.f16.f16.f16.f16 "
        "{%0,%1}, {%2,%3,%4,%5}, {%6,%7}, {%0,%1};\n"
        : "+r"(c[0]), "+r"(c[1])
        : "r"(a[0]), "r"(a[1]), "r"(a[2]), "r"(a[3]), "r"(b[0]), "r"(b[1]));
}

// ---------------- merged prep: encdec (bid<640) + Wv cvt (bid>=640) ----------------
__global__ void k_prep(const float* __restrict__ v, const float* __restrict__ t,
                       const float* __restrict__ W1, const float* __restrict__ b1,
                       const float* __restrict__ W2, const float* __restrict__ b2,
                       const float* __restrict__ Wv) {
    __shared__ float xr[4][512];
    int bid = blockIdx.x, tid = threadIdx.x;
    if (bid < 640) {
        int rg = bid >> 2, cq = bid & 3;
        const float *in, *W, *bs; float* out;
        if (rg < 128) { in = v + (size_t)rg * 2048; W = W1; bs = b1; out = g_enc + (size_t)rg * 2048; }
        else { in = t + (size_t)(rg - 128) * 2048; W = W2; bs = b2; out = g_dec + (size_t)(rg - 128) * 2048; }
        #pragma unroll
        for (int i = 0; i < 8; ++i) ((float*)xr)[i * 256 + tid] = in[i * 256 + tid];
        __syncthreads();
        int c = cq * 128 + (tid & 127);
        int rp = tid >> 7;
        float bb = bs[c];
        float a0 = bb, a1 = bb, a0b = 0.f, a1b = 0.f;
        #pragma unroll 4
        for (int d = 0; d < 512; d += 2) {
            float w0 = W[d * 512 + c], w1 = W[(d + 1) * 512 + c];
            a0  = fmaf(xr[rp][d],     w0, a0);
            a0b = fmaf(xr[rp][d + 1], w1, a0b);
            a1  = fmaf(xr[rp + 2][d],     w0, a1);
            a1b = fmaf(xr[rp + 2][d + 1], w1, a1b);
        }
        out[(size_t)rp * 512 + c] = a0 + a0b;
        out[(size_t)(rp + 2) * 512 + c] = a1 + a1b;
    } else {
        float (*tile)[33] = (float(*)[33])xr;
        int b2i = bid - 640;
        int bvi = b2i & 255, bd = b2i >> 8;
        int v0 = bvi * 32, d0 = bd * 32;
        int c = tid & 31, r8 = tid >> 5;
        #pragma unroll
        for (int i = 0; i < 4; ++i)
            tile[i * 8 + r8][c] = Wv[(size_t)(d0 + i * 8 + r8) * VSZ + v0 + c];
        __syncthreads();
        #pragma unroll
        for (int i = 0; i < 4; ++i)
            g_wvt[(size_t)(v0 + i * 8 + r8) * 512 + d0 + c] = __float2half(tile[c][i * 8 + r8]);
    }
}

// ---- main fp16 GEMM + fused log-softmax (at the fallback-HMMA dispatch floor) ----
// CTA: 128 rows x full V. 8 warps 2(M)x4(N), warp tile 64x64, f16 acc.
__global__ void __launch_bounds__(256, 1)
k_gemm2(const float* __restrict__ bv, float* __restrict__ out) {
    extern __shared__ char sm[];
    __shared__ float pmax[4][128], psum[4][128];
    __shared__ float rmax[128], rsum[128], slse[128];

    const uint32_t sA = smem_u32(sm);
    const uint32_t sB0 = sA + A_BYTES;
    int tid = threadIdx.x, lane = tid & 31, w = tid >> 5;
    int wm = w >> 2, wn = w & 3;
    int q = lane >> 2, l4 = lane & 3;
    int r0 = blockIdx.x * 128;

    // ---- build A tile (relu(enc+dec) -> fp16) ----
    #pragma unroll 1
    for (int i = 0; i < 32; ++i) {
        int idx = i * 256 + tid;
        int r = idx >> 6, g = idx & 63;
        int grow = r0 + r;
        const float* ep = g_enc + (size_t)(grow >> 6) * 512 + g * 8;
        const float* dp = g_dec + (size_t)(((grow >> 14) << 6) | (grow & 63)) * 512 + g * 8;
        float4 e0 = *(const float4*)ep, e1 = *(const float4*)(ep + 4);
        float4 d0 = *(const float4*)dp, d1 = *(const float4*)(dp + 4);
        __half2 p0 = __floats2half2_rn(fmaxf(e0.x + d0.x, 0.f), fmaxf(e0.y + d0.y, 0.f));
        __half2 p1 = __floats2half2_rn(fmaxf(e0.z + d0.z, 0.f), fmaxf(e0.w + d0.w, 0.f));
        __half2 p2 = __floats2half2_rn(fmaxf(e1.x + d1.x, 0.f), fmaxf(e1.y + d1.y, 0.f));
        __half2 p3 = __floats2half2_rn(fmaxf(e1.z + d1.z, 0.f), fmaxf(e1.w + d1.w, 0.f));
        uint4 u;
        u.x = *(unsigned*)&p0; u.y = *(unsigned*)&p1; u.z = *(unsigned*)&p2; u.w = *(unsigned*)&p3;
        *(uint4*)(sm + r * SA_STRB + g * 16) = u;
    }
    if (tid < 128) { rmax[tid] = -1e30f; rsum[tid] = 0.f; }

    const uint32_t aBase = sA + (wm * 64 + (lane & 15)) * SA_STRB + (lane >> 4) * 16;
    const int bN = (lane & 7) + ((lane >> 4) << 3);
    const uint32_t bKh = ((lane >> 3) & 1) * 16;
    const uint32_t bBase = sB0 + (wn * 64 + bN) * SB_STRB + bKh;

    uint32_t acc[4][8][2];   // fp16x2 accumulators

    // stage slab 0
    #pragma unroll
    for (int i = 0; i < 8; ++i) {
        int flat = i * 256 + tid;
        int n = flat >> 3, c = flat & 7;
        cpa16(sB0 + n * SB_STRB + c * 16, (const char*)g_wvt + (size_t)n * 1024 + c * 16);
    }
    CPA_COMMIT();

    #pragma unroll 1
    for (int s = 0; s < 256; ++s) {
        int vc = s >> 3, kb = s & 7, buf = s & 1;
        __syncthreads();
        if (s + 1 < 256) {
            int vn = (s + 1) >> 3, kn = (s + 1) & 7;
            uint32_t dst = sB0 + ((s + 1) & 1) * B_BYTES;
            const char* src = (const char*)g_wvt + (size_t)vn * 256 * 1024 + kn * 128;
            #pragma unroll
            for (int i = 0; i < 8; ++i) {
                int flat = i * 256 + tid;
                int n = flat >> 3, c = flat & 7;
                cpa16(dst + n * SB_STRB + c * 16, src + (size_t)n * 1024 + c * 16);
            }
            CPA_COMMIT();
            CPA_WAIT1();
        } else {
            CPA_WAIT0();
        }
        __syncthreads();

        if (kb == 0) {
            #pragma unroll
            for (int am = 0; am < 4; ++am)
                #pragma unroll
                for (int an = 0; an < 8; ++an) { acc[am][an][0] = 0u; acc[am][an][1] = 0u; }
        }

        uint32_t bB = bBase + buf * B_BYTES;
        uint32_t aK = aBase + kb * 128;
        #pragma unroll
        for (int ks = 0; ks < 4; ++ks) {
            uint32_t afr[4][4], bfr[4][4];
            #pragma unroll
            for (int am = 0; am < 4; ++am) ldsm4(afr[am], aK + am * 16 * SA_STRB + ks * 32);
            #pragma unroll
            for (int t = 0; t < 4; ++t) ldsm4(bfr[t], bB + t * 16 * SB_STRB + ks * 32);
            #pragma unroll
            for (int am = 0; am < 4; ++am)
                #pragma unroll
                for (int t = 0; t < 4; ++t) {
                    mma_h(acc[am][2 * t],     afr[am], &bfr[t][0]);
                    mma_h(acc[am][2 * t + 1], afr[am], &bfr[t][2]);
                }
        }

        if (kb == 7) {
            int v0 = vc * 256;
            float2 bvv[8];
            #pragma unroll
            for (int an = 0; an < 8; ++an)
                bvv[an] = *(const float2*)&bv[v0 + wn * 64 + an * 8 + l4 * 2];
            #pragma unroll
            for (int am = 0; am < 4; ++am) {
                int rowl = wm * 64 + am * 16 + q;
                size_t gr0 = (size_t)(r0 + rowl) << 13;
                size_t gr1 = gr0 + (8u << 13);
                float mx0 = -1e30f, mx1 = -1e30f;
                float z[8][4];
                #pragma unroll
                for (int an = 0; an < 8; ++an) {
                    float2 f0 = __half22float2(*(__half2*)&acc[am][an][0]);
                    float2 f1 = __half22float2(*(__half2*)&acc[am][an][1]);
                    z[an][0] = f0.x + bvv[an].x; z[an][1] = f0.y + bvv[an].y;
                    z[an][2] = f1.x + bvv[an].x; z[an][3] = f1.y + bvv[an].y;
                    size_t coff = v0 + wn * 64 + an * 8 + l4 * 2;
                    *(float2*)&out[gr0 + coff] = make_float2(z[an][0], z[an][1]);
                    *(float2*)&out[gr1 + coff] = make_float2(z[an][2], z[an][3]);
                    mx0 = fmaxf(mx0, fmaxf(z[an][0], z[an][1]));
                    mx1 = fmaxf(mx1, fmaxf(z[an][2], z[an][3]));
                }
                mx0 = fmaxf(mx0, __shfl_xor_sync(~0u, mx0, 1));
                mx0 = fmaxf(mx0, __shfl_xor_sync(~0u, mx0, 2));
                mx1 = fmaxf(mx1, __shfl_xor_sync(~0u, mx1, 1));
                mx1 = fmaxf(mx1, __shfl_xor_sync(~0u, mx1, 2));
                float s0 = 0.f, s1 = 0.f;
                #pragma unroll
                for (int an = 0; an < 8; ++an) {
                    s0 += __expf(z[an][0] - mx0) + __expf(z[an][1] - mx0);
                    s1 += __expf(z[an][2] - mx1) + __expf(z[an][3] - mx1);
                }
                s0 += __shfl_xor_sync(~0u, s0, 1);
                s0 += __shfl_xor_sync(~0u, s0, 2);
                s1 += __shfl_xor_sync(~0u, s1, 1);
                s1 += __shfl_xor_sync(~0u, s1, 2);
                if (l4 == 0) {
                    pmax[wn][rowl] = mx0;     psum[wn][rowl] = s0;
                    pmax[wn][rowl + 8] = mx1; psum[wn][rowl + 8] = s1;
                }
            }
            __syncthreads();
            if (tid < 128) {
                float m0 = pmax[0][tid], m1 = pmax[1][tid];
                float m2 = pmax[2][tid], m3 = pmax[3][tid];
                float mo = rmax[tid];
                float mn = fmaxf(fmaxf(fmaxf(m0, m1), fmaxf(m2, m3)), mo);
                rsum[tid] = rsum[tid] * __expf(mo - mn)
                          + psum[0][tid] * __expf(m0 - mn)
                          + psum[1][tid] * __expf(m1 - mn)
                          + psum[2][tid] * __expf(m2 - mn)
                          + psum[3][tid] * __expf(m3 - mn);
                rmax[tid] = mn;
            }
        }
    }

    // ---- fused fixup: out -= lse over this CTA's 128 rows ----
    __syncthreads();
    if (tid < 128) slse[tid] = rmax[tid] + logf(rsum[tid]);
    __syncthreads();
    float4* ob = (float4*)(out + ((size_t)r0 << 13));
    #pragma unroll 4
    for (int it = 0; it < 1024; ++it) {
        int idx = it * 256 + tid;
        float l = slse[idx >> 11];
        float4 x = ob[idx];
        x.x -= l; x.y -= l; x.z -= l; x.w -= l;
        ob[idx] = x;
    }
}

extern "C" void kernel_launch(void* const* d_in, const int* in_sizes, int n_in,
                              void* d_out, int out_size) {
    (void)in_sizes; (void)n_in; (void)out_size;
    const float* v  = (const float*)d_in[0];
    const float* t  = (const float*)d_in[1];
    const float* W1 = (const float*)d_in[2];
    const float* b1 = (const float*)d_in[3];
    const float* W2 = (const float*)d_in[4];
    const float* b2 = (const float*)d_in[5];
    const float* Wv = (const float*)d_in[6];
    const float* bvp = (const float*)d_in[7];
    float* out = (float*)d_out;

    k_prep<<<4736, 256>>>(v, t, W1, b1, W2, b2, Wv);
    cudaFuncSetAttribute(k_gemm2, cudaFuncAttributeMaxDynamicSharedMemorySize, DYN_SMEM);
    k_gemm2<<<256, 256, DYN_SMEM>>>(bvp, out);
}